// round 12
// baseline (speedup 1.0000x reference)
#include <cuda_runtime.h>
#include <cuda_fp16.h>
#include <stdint.h>

// ---------------------------------------------------------------------------
// Problem constants
// ---------------------------------------------------------------------------
#define Bb 8
#define Tt 2048
#define Mm 1024
#define Ff 2048
#define Ee 8
#define Ss 16384
#define CAP 2048
#define ECAP 16384
#define DROPPED 0x7FFFFFFF

// All single-term fp16 storage (hi):
__device__ __align__(128) __half g_dk_h[(size_t)ECAP * 1024];
__device__ __align__(128) __half g_dr_h[(size_t)ECAP * 1024];
__device__ __align__(128) __half g_h_h [(size_t)ECAP * 2048];
__device__ __align__(128) __half g_Wk_h[(size_t)Ee * 2048 * 1024];
__device__ __align__(128) __half g_Wv_h[(size_t)Ee * 1024 * 2048];
__device__ __align__(128) __half g_Wr_h[(size_t)Ee * 1024 * 1024];
__device__ float g_kv[(size_t)ECAP * Mm];
__device__ int   g_slot2tok[ECAP];
__device__ int   g_tok2slot[Ss];

// ---------------------------------------------------------------------------
// PTX helpers
// ---------------------------------------------------------------------------
__device__ __forceinline__ uint32_t smem_u32(const void* p) {
    uint32_t a;
    asm("{ .reg .u64 t; cvta.to.shared.u64 t, %1; cvt.u32.u64 %0, t; }" : "=r"(a) : "l"(p));
    return a;
}
__device__ __forceinline__ void cp16(uint32_t s, const void* g) {
    asm volatile("cp.async.cg.shared.global [%0], [%1], 16;" :: "r"(s), "l"(g) : "memory");
}
#define CP_COMMIT() asm volatile("cp.async.commit_group;" ::: "memory")
#define CP_WAIT2()  asm volatile("cp.async.wait_group 2;" ::: "memory")

#define LDSM_X4(r, a) \
    asm volatile("ldmatrix.sync.aligned.m8n8.x4.shared.b16 {%0,%1,%2,%3}, [%4];" \
        : "=r"((r)[0]), "=r"((r)[1]), "=r"((r)[2]), "=r"((r)[3]) : "r"(a))

__device__ __forceinline__ void mma_fp16(float* c, const uint32_t* a,
                                         uint32_t b0, uint32_t b1) {
    asm volatile(
        "mma.sync.aligned.m16n8k16.row.col.f32.f16.f16.f32 "
        "{%0,%1,%2,%3}, {%4,%5,%6,%7}, {%8,%9}, {%0,%1,%2,%3};"
        : "+f"(c[0]), "+f"(c[1]), "+f"(c[2]), "+f"(c[3])
        : "r"(a[0]), "r"(a[1]), "r"(a[2]), "r"(a[3]), "r"(b0), "r"(b1));
}

// ---------------------------------------------------------------------------
// Routing
// ---------------------------------------------------------------------------
__global__ void route_kernel(const int* __restrict__ tok) {
    __shared__ int cnt[256][8];
    const int t = threadIdx.x;
    for (int i = t; i < ECAP; i += 256) g_slot2tok[i] = -1;
    const int base = t * 64;
    int c[8] = {0,0,0,0,0,0,0,0};
    for (int i = 0; i < 64; ++i) { int e = (tok[base + i] * 5099) & 7; c[e]++; }
    #pragma unroll
    for (int e = 0; e < 8; ++e) cnt[t][e] = c[e];
    __syncthreads();
    if (t < 8) {
        int run = 0;
        for (int j = 0; j < 256; ++j) { int v = cnt[j][t]; cnt[j][t] = run; run += v; }
    }
    __syncthreads();
    int run[8];
    #pragma unroll
    for (int e = 0; e < 8; ++e) run[e] = cnt[t][e];
    for (int i = 0; i < 64; ++i) {
        int s = base + i;
        int e = (tok[s] * 5099) & 7;
        int pos = run[e]++;
        if (pos < CAP) { int slot = e * CAP + pos; g_tok2slot[s] = slot; g_slot2tok[slot] = s; }
        else g_tok2slot[s] = DROPPED;
    }
}

// ---------------------------------------------------------------------------
// Dispatch: token-shift mix; dk & dr fp16 hi only
// ---------------------------------------------------------------------------
__global__ void dispatch_kernel(const float* __restrict__ x,
                                const float* __restrict__ shift,
                                const float* __restrict__ maak,
                                const float* __restrict__ maar) {
    const int slot = blockIdx.x;
    const int j = threadIdx.x * 4;
    __half* rk = g_dk_h + (size_t)slot * 1024;
    __half* rr = g_dr_h + (size_t)slot * 1024;
    const int tokidx = g_slot2tok[slot];
    float4 dk, dr;
    if (tokidx < 0) {
        dk = dr = make_float4(0.f, 0.f, 0.f, 0.f);
    } else {
        const int b = tokidx / Tt;
        const int t = tokidx % Tt;
        float4 xv = *(const float4*)&x[(size_t)tokidx * Mm + j];
        float4 xp;
        if (t == 0) xp = *(const float4*)&shift[(size_t)b * Mm + j];
        else        xp = *(const float4*)&x[(size_t)(tokidx - 1) * Mm + j];
        float4 mk = *(const float4*)&maak[j];
        float4 mr = *(const float4*)&maar[j];
        float4 dx = make_float4(xp.x - xv.x, xp.y - xv.y, xp.z - xv.z, xp.w - xv.w);
        dk = make_float4(fmaf(dx.x, mk.x, xv.x), fmaf(dx.y, mk.y, xv.y),
                         fmaf(dx.z, mk.z, xv.z), fmaf(dx.w, mk.w, xv.w));
        dr = make_float4(fmaf(dx.x, mr.x, xv.x), fmaf(dx.y, mr.y, xv.y),
                         fmaf(dx.z, mr.z, xv.z), fmaf(dx.w, mr.w, xv.w));
    }
    *(__half2*)(rk + j)     = __halves2half2(__float2half(dk.x), __float2half(dk.y));
    *(__half2*)(rk + j + 2) = __halves2half2(__float2half(dk.z), __float2half(dk.w));
    *(__half2*)(rr + j)     = __halves2half2(__float2half(dr.x), __float2half(dr.y));
    *(__half2*)(rr + j + 2) = __halves2half2(__float2half(dr.z), __float2half(dr.w));
}

// ---------------------------------------------------------------------------
// Weight transpose: W [E][K][N] fp32 -> W' [E][N][K] fp16 (hi only)
// ---------------------------------------------------------------------------
__global__ void wconv_fp16_kernel(const float* __restrict__ W,
                                  __half* __restrict__ out, int K, int N) {
    __shared__ __half tile[64][33];
    const int e = blockIdx.z;
    const float* Wp = W + (size_t)e * K * N;
    __half* op = out + (size_t)e * N * K;
    const int k0 = blockIdx.y * 64, n0 = blockIdx.x * 32;
    const int tx = threadIdx.x, ty = threadIdx.y;   // (32, 8)
    #pragma unroll
    for (int i = 0; i < 8; ++i)
        tile[ty + i * 8][tx] = __float2half(Wp[(size_t)(k0 + ty + i * 8) * N + n0 + tx]);
    __syncthreads();
    #pragma unroll
    for (int j = 0; j < 4; ++j) {
        const int n = ty + j * 8;
        __half2 v = __halves2half2(tile[tx * 2][n], tile[tx * 2 + 1][n]);
        *(__half2*)&op[(size_t)(n0 + n) * K + k0 + tx * 2] = v;
    }
}

// ---------------------------------------------------------------------------
// Single-term fp16 HMMA GEMM — 64x64 warp tiles to relieve smem crossbar.
// Block tile 128x128, 128 thr, 4 warps (2M x 2N), warp 64x64, 2 CTA/SM.
// Stage = A 8KB + B 8KB = 16KB, 4 stages (64KB).
// EPI 0: relu^2 -> fp16 into Cb. EPI 1: f32 copy to Cf.
// EPI 3: sigmoid * kv[slot] scattered to out[token] (fused combine).
// ---------------------------------------------------------------------------
constexpr int STAGE     = 16384;
constexpr int GEMM_SMEM = 4 * STAGE;   // 64 KB

template<int EPI, int TCH>
__global__ void __launch_bounds__(128, 2)
gemm_mma(const __half* __restrict__ Ag, const __half* __restrict__ Bg,
         float* __restrict__ Cf, __half* __restrict__ Cb,
         const float* __restrict__ KV, int N) {
    constexpr int K     = TCH * 32;
    constexpr int ROW_B = 2 * K;
    constexpr int BOFF  = 8192;

    extern __shared__ __align__(1024) char smem[];
    const uint32_t sb = smem_u32(smem);
    const int tid = threadIdx.x;
    const int lane = tid & 31, warp = tid >> 5;
    const int wm = warp & 1, wn = warp >> 1;
    const int e = blockIdx.z;
    const int bm = blockIdx.y * 128, bn = blockIdx.x * 128;

    const char* A = (const char*)Ag + ((size_t)e * 2048 + bm) * ROW_B;
    const char* B = (const char*)Bg + ((size_t)e * N + bn) * ROW_B;

    // loader: 128 threads; each region 128 rows x 64B; 4 rows/thread/region
    const int lr = tid >> 2, lc = tid & 3;   // lr in 0..31
    const uint32_t swL = (uint32_t)(lr * 64 + ((lc ^ ((lr >> 1) & 3)) << 4));
    const uint32_t cbL = (uint32_t)(lc * 16);

    auto load_stage = [&](int st, int kt) {
        const int colB = kt * 64;
        const uint32_t b = sb + st * STAGE;
        #pragma unroll
        for (int i = 0; i < 4; ++i)   // +32 rows: (row>>1)&3 invariant
            cp16(b + swL + i * 2048,
                 A + (size_t)(lr + i * 32) * ROW_B + colB + cbL);
        #pragma unroll
        for (int i = 0; i < 4; ++i)
            cp16(b + BOFF + swL + i * 2048,
                 B + (size_t)(lr + i * 32) * ROW_B + colB + cbL);
    };

    // ldmatrix offsets: warp tile 64 rows (4 m16 frags, +16 rows = +1024B)
    const int rowA0 = wm * 64 + (lane & 15);
    const uint32_t aOff = (uint32_t)(rowA0 * 64 +
                          (((lane >> 4) ^ ((rowA0 >> 1) & 3)) << 4));
    const int rowB0 = wn * 64 + (lane & 7) + ((lane >> 4) << 3);
    const uint32_t bOff = (uint32_t)(rowB0 * 64 +
                          ((((lane >> 3) & 1) ^ ((rowB0 >> 1) & 3)) << 4));

    float acc[4][8][4];
    #pragma unroll
    for (int i = 0; i < 4; ++i)
        #pragma unroll
        for (int j = 0; j < 8; ++j)
            #pragma unroll
            for (int k = 0; k < 4; ++k) acc[i][j][k] = 0.f;

    load_stage(0, 0); CP_COMMIT();
    load_stage(1, 1); CP_COMMIT();
    load_stage(2, 2); CP_COMMIT();

    for (int kt = 0; kt < TCH; ++kt) {
        CP_WAIT2();
        __syncthreads();
        if (kt + 3 < TCH) load_stage((kt + 3) & 3, kt + 3);
        CP_COMMIT();

        const uint32_t stb = sb + (kt & 3) * STAGE;
        #pragma unroll
        for (int ks = 0; ks < 2; ++ks) {
            const uint32_t kx = ks * 32;
            uint32_t a[4][4];
            #pragma unroll
            for (int mi = 0; mi < 4; ++mi)
                LDSM_X4(a[mi], (stb + aOff + mi * 1024) ^ kx);
            uint32_t b[4][4];
            #pragma unroll
            for (int nf2 = 0; nf2 < 4; ++nf2)
                LDSM_X4(b[nf2], (stb + BOFF + bOff + nf2 * 1024) ^ kx);
            #pragma unroll
            for (int mi = 0; mi < 4; ++mi)
                #pragma unroll
                for (int nf2 = 0; nf2 < 4; ++nf2) {
                    mma_fp16(acc[mi][nf2 * 2 + 0], a[mi], b[nf2][0], b[nf2][1]);
                    mma_fp16(acc[mi][nf2 * 2 + 1], a[mi], b[nf2][2], b[nf2][3]);
                }
        }
    }

    // Epilogue
    #pragma unroll
    for (int mi = 0; mi < 4; ++mi) {
        #pragma unroll
        for (int nf = 0; nf < 8; ++nf) {
            const float* c = acc[mi][nf];
            const int col = bn + wn * 64 + nf * 8 + (lane & 3) * 2;
            const int row0 = bm + wm * 64 + mi * 16 + (lane >> 2);
            #pragma unroll
            for (int hh = 0; hh < 2; ++hh) {
                const int row = row0 + hh * 8;
                float v0 = c[hh * 2 + 0], v1 = c[hh * 2 + 1];
                if (EPI == 0) {
                    v0 = v0 > 0.f ? v0 * v0 : 0.f;
                    v1 = v1 > 0.f ? v1 * v1 : 0.f;
                    __half* p = Cb + ((size_t)e * 2048 + row) * (size_t)N + col;
                    *(__half2*)p = __halves2half2(__float2half(v0), __float2half(v1));
                } else if (EPI == 1) {
                    float* p = Cf + ((size_t)e * 2048 + row) * (size_t)N + col;
                    *(float2*)p = make_float2(v0, v1);
                } else {   // EPI == 3: fused sigmoid * kv -> out[token]
                    const int slot = e * 2048 + row;
                    const int tokidx = g_slot2tok[slot];
                    if (tokidx >= 0) {
                        float2 kv = *(const float2*)&KV[(size_t)slot * N + col];
                        v0 = kv.x / (1.f + __expf(-v0));
                        v1 = kv.y / (1.f + __expf(-v1));
                        *(float2*)&Cf[(size_t)tokidx * N + col] = make_float2(v0, v1);
                    }
                }
            }
        }
    }
}

// ---------------------------------------------------------------------------
// Zero-fill for dropped tokens; shift state
// ---------------------------------------------------------------------------
__global__ void zero_dropped_kernel(float* __restrict__ out) {
    const int s = blockIdx.x;
    if (g_tok2slot[s] != DROPPED) return;
    const int j = threadIdx.x * 4;
    *(float4*)&out[(size_t)s * Mm + j] = make_float4(0.f, 0.f, 0.f, 0.f);
}
__global__ void shift_kernel(const float* __restrict__ x, float* __restrict__ out) {
    const int b = blockIdx.x;
    const int j = threadIdx.x * 4;
    *(float4*)&out[(size_t)Ss * Mm + (size_t)b * Mm + j] =
        *(const float4*)&x[((size_t)b * Tt + (Tt - 1)) * Mm + j];
}

// ---------------------------------------------------------------------------
// Host
// ---------------------------------------------------------------------------
extern "C" void kernel_launch(void* const* d_in, const int* in_sizes, int n_in,
                              void* d_out, int out_size) {
    const float* x     = (const float*)d_in[0];
    const int*   tok   = (const int*)  d_in[1];
    const float* shift = (const float*)d_in[2];
    const float* maak  = (const float*)d_in[3];
    const float* maar  = (const float*)d_in[4];
    const float* Wk    = (const float*)d_in[5];
    const float* Wv    = (const float*)d_in[6];
    const float* Wr    = (const float*)d_in[7];
    float* out = (float*)d_out;

    void *dkh, *drh, *hh, *wkh, *wvh, *wrh, *kvp;
    cudaGetSymbolAddress(&dkh, g_dk_h);
    cudaGetSymbolAddress(&drh, g_dr_h);
    cudaGetSymbolAddress(&hh,  g_h_h);
    cudaGetSymbolAddress(&wkh, g_Wk_h);
    cudaGetSymbolAddress(&wvh, g_Wv_h);
    cudaGetSymbolAddress(&wrh, g_Wr_h);
    cudaGetSymbolAddress(&kvp, g_kv);

    cudaFuncSetAttribute((const void*)gemm_mma<0, 32>,
                         cudaFuncAttributeMaxDynamicSharedMemorySize, GEMM_SMEM);
    cudaFuncSetAttribute((const void*)gemm_mma<1, 64>,
                         cudaFuncAttributeMaxDynamicSharedMemorySize, GEMM_SMEM);
    cudaFuncSetAttribute((const void*)gemm_mma<3, 32>,
                         cudaFuncAttributeMaxDynamicSharedMemorySize, GEMM_SMEM);

    route_kernel<<<1, 256>>>(tok);
    dispatch_kernel<<<ECAP, 256>>>(x, shift, maak, maar);
    wconv_fp16_kernel<<<dim3(64, 16, 8), dim3(32, 8)>>>(Wk, (__half*)wkh, 1024, 2048);
    wconv_fp16_kernel<<<dim3(32, 32, 8), dim3(32, 8)>>>(Wv, (__half*)wvh, 2048, 1024);
    wconv_fp16_kernel<<<dim3(32, 16, 8), dim3(32, 8)>>>(Wr, (__half*)wrh, 1024, 1024);

    // h = relu^2(dk @ Wk): K=1024, N=2048
    gemm_mma<0, 32><<<dim3(16, 16, 8), 128, GEMM_SMEM>>>(
        (const __half*)dkh, (const __half*)wkh, nullptr, (__half*)hh, nullptr, 2048);
    // kv = h @ Wv: K=2048, N=1024
    gemm_mma<1, 64><<<dim3(8, 16, 8), 128, GEMM_SMEM>>>(
        (const __half*)hh, (const __half*)wvh, (float*)kvp, nullptr, nullptr, 1024);
    // out[token] = sigmoid(dr @ Wr) * kv (fused combine): K=1024, N=1024
    gemm_mma<3, 32><<<dim3(8, 16, 8), 128, GEMM_SMEM>>>(
        (const __half*)drh, (const __half*)wrh, out, nullptr,
        (const float*)kvp, 1024);

    zero_dropped_kernel<<<Ss, 256>>>(out);
    if ((size_t)out_size >= (size_t)Ss * Mm + (size_t)Bb * Mm)
        shift_kernel<<<Bb, 256>>>(x, out);
}

// round 13
// speedup vs baseline: 1.1629x; 1.1629x over previous
#include <cuda_runtime.h>
#include <cuda_fp16.h>
#include <stdint.h>

// ---------------------------------------------------------------------------
// Problem constants
// ---------------------------------------------------------------------------
#define Bb 8
#define Tt 2048
#define Mm 1024
#define Ff 2048
#define Ee 8
#define Ss 16384
#define CAP 2048
#define ECAP 16384
#define DROPPED 0x7FFFFFFF

// All single-term fp16 storage (hi):
__device__ __align__(128) __half g_dk_h[(size_t)ECAP * 1024];
__device__ __align__(128) __half g_dr_h[(size_t)ECAP * 1024];
__device__ __align__(128) __half g_h_h [(size_t)ECAP * 2048];
__device__ __align__(128) __half g_Wk_h[(size_t)Ee * 2048 * 1024];
__device__ __align__(128) __half g_Wv_h[(size_t)Ee * 1024 * 2048];
__device__ __align__(128) __half g_Wr_h[(size_t)Ee * 1024 * 1024];
__device__ int g_slot2tok[ECAP];
__device__ int g_tok2slot[Ss];

// ---------------------------------------------------------------------------
// PTX helpers
// ---------------------------------------------------------------------------
__device__ __forceinline__ uint32_t smem_u32(const void* p) {
    uint32_t a;
    asm("{ .reg .u64 t; cvta.to.shared.u64 t, %1; cvt.u32.u64 %0, t; }" : "=r"(a) : "l"(p));
    return a;
}
__device__ __forceinline__ void cp16(uint32_t s, const void* g) {
    asm volatile("cp.async.cg.shared.global [%0], [%1], 16;" :: "r"(s), "l"(g) : "memory");
}
#define CP_COMMIT() asm volatile("cp.async.commit_group;" ::: "memory")
#define CP_WAIT2()  asm volatile("cp.async.wait_group 2;" ::: "memory")
#define CP_WAIT0()  asm volatile("cp.async.wait_group 0;" ::: "memory")

#define LDSM_X4(r, a) \
    asm volatile("ldmatrix.sync.aligned.m8n8.x4.shared.b16 {%0,%1,%2,%3}, [%4];" \
        : "=r"((r)[0]), "=r"((r)[1]), "=r"((r)[2]), "=r"((r)[3]) : "r"(a))

__device__ __forceinline__ void mma_fp16(float* c, const uint32_t* a,
                                         uint32_t b0, uint32_t b1) {
    asm volatile(
        "mma.sync.aligned.m16n8k16.row.col.f32.f16.f16.f32 "
        "{%0,%1,%2,%3}, {%4,%5,%6,%7}, {%8,%9}, {%0,%1,%2,%3};"
        : "+f"(c[0]), "+f"(c[1]), "+f"(c[2]), "+f"(c[3])
        : "r"(a[0]), "r"(a[1]), "r"(a[2]), "r"(a[3]), "r"(b0), "r"(b1));
}

// ---------------------------------------------------------------------------
// Routing
// ---------------------------------------------------------------------------
__global__ void route_kernel(const int* __restrict__ tok) {
    __shared__ int cnt[256][8];
    const int t = threadIdx.x;
    for (int i = t; i < ECAP; i += 256) g_slot2tok[i] = -1;
    const int base = t * 64;
    int c[8] = {0,0,0,0,0,0,0,0};
    for (int i = 0; i < 64; ++i) { int e = (tok[base + i] * 5099) & 7; c[e]++; }
    #pragma unroll
    for (int e = 0; e < 8; ++e) cnt[t][e] = c[e];
    __syncthreads();
    if (t < 8) {
        int run = 0;
        for (int j = 0; j < 256; ++j) { int v = cnt[j][t]; cnt[j][t] = run; run += v; }
    }
    __syncthreads();
    int run[8];
    #pragma unroll
    for (int e = 0; e < 8; ++e) run[e] = cnt[t][e];
    for (int i = 0; i < 64; ++i) {
        int s = base + i;
        int e = (tok[s] * 5099) & 7;
        int pos = run[e]++;
        if (pos < CAP) { int slot = e * CAP + pos; g_tok2slot[s] = slot; g_slot2tok[slot] = s; }
        else g_tok2slot[s] = DROPPED;
    }
}

// ---------------------------------------------------------------------------
// Dispatch: token-shift mix; dk & dr fp16 hi only
// ---------------------------------------------------------------------------
__global__ void dispatch_kernel(const float* __restrict__ x,
                                const float* __restrict__ shift,
                                const float* __restrict__ maak,
                                const float* __restrict__ maar) {
    const int slot = blockIdx.x;
    const int j = threadIdx.x * 4;
    __half* rk = g_dk_h + (size_t)slot * 1024;
    __half* rr = g_dr_h + (size_t)slot * 1024;
    const int tokidx = g_slot2tok[slot];
    float4 dk, dr;
    if (tokidx < 0) {
        dk = dr = make_float4(0.f, 0.f, 0.f, 0.f);
    } else {
        const int b = tokidx / Tt;
        const int t = tokidx % Tt;
        float4 xv = *(const float4*)&x[(size_t)tokidx * Mm + j];
        float4 xp;
        if (t == 0) xp = *(const float4*)&shift[(size_t)b * Mm + j];
        else        xp = *(const float4*)&x[(size_t)(tokidx - 1) * Mm + j];
        float4 mk = *(const float4*)&maak[j];
        float4 mr = *(const float4*)&maar[j];
        float4 dx = make_float4(xp.x - xv.x, xp.y - xv.y, xp.z - xv.z, xp.w - xv.w);
        dk = make_float4(fmaf(dx.x, mk.x, xv.x), fmaf(dx.y, mk.y, xv.y),
                         fmaf(dx.z, mk.z, xv.z), fmaf(dx.w, mk.w, xv.w));
        dr = make_float4(fmaf(dx.x, mr.x, xv.x), fmaf(dx.y, mr.y, xv.y),
                         fmaf(dx.z, mr.z, xv.z), fmaf(dx.w, mr.w, xv.w));
    }
    *(__half2*)(rk + j)     = __halves2half2(__float2half(dk.x), __float2half(dk.y));
    *(__half2*)(rk + j + 2) = __halves2half2(__float2half(dk.z), __float2half(dk.w));
    *(__half2*)(rr + j)     = __halves2half2(__float2half(dr.x), __float2half(dr.y));
    *(__half2*)(rr + j + 2) = __halves2half2(__float2half(dr.z), __float2half(dr.w));
}

// ---------------------------------------------------------------------------
// Weight transpose: W [E][K][N] fp32 -> W' [E][N][K] fp16 (hi only)
// ---------------------------------------------------------------------------
__global__ void wconv_fp16_kernel(const float* __restrict__ W,
                                  __half* __restrict__ out, int K, int N) {
    __shared__ __half tile[64][33];
    const int e = blockIdx.z;
    const float* Wp = W + (size_t)e * K * N;
    __half* op = out + (size_t)e * N * K;
    const int k0 = blockIdx.y * 64, n0 = blockIdx.x * 32;
    const int tx = threadIdx.x, ty = threadIdx.y;   // (32, 8)
    #pragma unroll
    for (int i = 0; i < 8; ++i)
        tile[ty + i * 8][tx] = __float2half(Wp[(size_t)(k0 + ty + i * 8) * N + n0 + tx]);
    __syncthreads();
    #pragma unroll
    for (int j = 0; j < 4; ++j) {
        const int n = ty + j * 8;
        __half2 v = __halves2half2(tile[tx * 2][n], tile[tx * 2 + 1][n]);
        *(__half2*)&op[(size_t)(n0 + n) * K + k0 + tx * 2] = v;
    }
}

// ---------------------------------------------------------------------------
// Shared GEMM mainloop (round-11 geometry): 128x128 tile, 256 thr, 8 warps
// (4M x 2N), warp 32x64, 4-stage 16KB pipeline. Accumulates into acc.
// ---------------------------------------------------------------------------
constexpr int STAGE = 16384;
constexpr int BOFF  = 8192;

template<int TCH, int ROW_B>
__device__ __forceinline__ void gemm_mainloop(
    uint32_t sb, const char* A, const char* B,
    int lr, uint32_t swL0, uint32_t swL1, uint32_t cbL,
    uint32_t aOff, uint32_t bOff, float acc[2][8][4])
{
    auto load_stage = [&](int st, int kt) {
        const int colB = kt * 64;
        const uint32_t b = sb + st * STAGE;
        cp16(b + swL0,        A + (size_t)lr * ROW_B + colB + cbL);
        cp16(b + swL1,        A + (size_t)(lr + 64) * ROW_B + colB + cbL);
        cp16(b + BOFF + swL0, B + (size_t)lr * ROW_B + colB + cbL);
        cp16(b + BOFF + swL1, B + (size_t)(lr + 64) * ROW_B + colB + cbL);
    };

    load_stage(0, 0); CP_COMMIT();
    load_stage(1, 1); CP_COMMIT();
    load_stage(2, 2); CP_COMMIT();

    for (int kt = 0; kt < TCH; ++kt) {
        CP_WAIT2();
        __syncthreads();
        if (kt + 3 < TCH) load_stage((kt + 3) & 3, kt + 3);
        CP_COMMIT();

        const uint32_t stb = sb + (kt & 3) * STAGE;
        #pragma unroll
        for (int ks = 0; ks < 2; ++ks) {
            const uint32_t kx = ks * 32;
            uint32_t a[2][4];
            #pragma unroll
            for (int mi = 0; mi < 2; ++mi)
                LDSM_X4(a[mi], (stb + aOff + mi * 1024) ^ kx);
            uint32_t b[4][4];
            #pragma unroll
            for (int nf2 = 0; nf2 < 4; ++nf2)
                LDSM_X4(b[nf2], (stb + BOFF + bOff + nf2 * 1024) ^ kx);
            #pragma unroll
            for (int mi = 0; mi < 2; ++mi)
                #pragma unroll
                for (int nf2 = 0; nf2 < 4; ++nf2) {
                    mma_fp16(acc[mi][nf2 * 2 + 0], a[mi], b[nf2][0], b[nf2][1]);
                    mma_fp16(acc[mi][nf2 * 2 + 1], a[mi], b[nf2][2], b[nf2][3]);
                }
        }
    }
    CP_WAIT0();
}

// ---------------------------------------------------------------------------
// GEMM1: h = relu^2(dk @ Wk), fp16 out. Round-11 kernel unchanged.
// ---------------------------------------------------------------------------
constexpr int GEMM1_SMEM = 4 * STAGE;   // 64 KB

__global__ void __launch_bounds__(256, 2)
gemm1_kernel(const __half* __restrict__ Ag, const __half* __restrict__ Bg,
             __half* __restrict__ Cb) {
    constexpr int TCH = 32, N = 2048, ROW_B = 2048;
    extern __shared__ __align__(1024) char smem[];
    const uint32_t sb = smem_u32(smem);
    const int tid = threadIdx.x;
    const int lane = tid & 31, warp = tid >> 5;
    const int wm = warp & 3, wn = warp >> 2;
    const int e = blockIdx.z;
    const int bm = blockIdx.y * 128, bn = blockIdx.x * 128;

    const char* A = (const char*)Ag + ((size_t)e * 2048 + bm) * ROW_B;
    const char* B = (const char*)Bg + ((size_t)e * N + bn) * ROW_B;

    const int lr = tid >> 2, lc = tid & 3;
    const uint32_t swL0 = (uint32_t)(lr * 64 + ((lc ^ ((lr >> 1) & 3)) << 4));
    const uint32_t swL1 = (uint32_t)((lr + 64) * 64 + ((lc ^ (((lr + 64) >> 1) & 3)) << 4));
    const uint32_t cbL = (uint32_t)(lc * 16);

    const int rowA0 = wm * 32 + (lane & 15);
    const uint32_t aOff = (uint32_t)(rowA0 * 64 + (((lane >> 4) ^ ((rowA0 >> 1) & 3)) << 4));
    const int rowB0 = wn * 64 + (lane & 7) + ((lane >> 4) << 3);
    const uint32_t bOff = (uint32_t)(rowB0 * 64 + ((((lane >> 3) & 1) ^ ((rowB0 >> 1) & 3)) << 4));

    float acc[2][8][4];
    #pragma unroll
    for (int i = 0; i < 2; ++i)
        #pragma unroll
        for (int j = 0; j < 8; ++j)
            #pragma unroll
            for (int k = 0; k < 4; ++k) acc[i][j][k] = 0.f;

    gemm_mainloop<TCH, ROW_B>(sb, A, B, lr, swL0, swL1, cbL, aOff, bOff, acc);

    #pragma unroll
    for (int mi = 0; mi < 2; ++mi)
        #pragma unroll
        for (int nf = 0; nf < 8; ++nf) {
            const float* c = acc[mi][nf];
            const int col = bn + wn * 64 + nf * 8 + (lane & 3) * 2;
            const int row0 = bm + wm * 32 + mi * 16 + (lane >> 2);
            #pragma unroll
            for (int hh = 0; hh < 2; ++hh) {
                const int row = row0 + hh * 8;
                float v0 = c[hh * 2 + 0], v1 = c[hh * 2 + 1];
                v0 = v0 > 0.f ? v0 * v0 : 0.f;
                v1 = v1 > 0.f ? v1 * v1 : 0.f;
                __half* p = Cb + ((size_t)e * 2048 + row) * (size_t)N + col;
                *(__half2*)p = __halves2half2(__float2half(v0), __float2half(v1));
            }
        }
}

// ---------------------------------------------------------------------------
// GEMM23 fused: Phase A r = sigmoid(dr @ Wr) -> smem scratch (fp16),
// Phase B kv = h @ Wv (registers), epilogue out[tok] = r * kv.
// scratch: 128 rows x 272B (conflict-free padding) = 34816B.
// smem total = 64KB stages + 34KB scratch = 100352B, 2 CTA/SM.
// ---------------------------------------------------------------------------
constexpr int SCRATCH_OFF = 4 * STAGE;          // 65536
constexpr int SCRATCH_PITCH = 272;              // bytes per row
constexpr int GEMM23_SMEM = SCRATCH_OFF + 128 * SCRATCH_PITCH;  // 100352

__global__ void __launch_bounds__(256, 2)
gemm23_kernel(const __half* __restrict__ DR, const __half* __restrict__ WR,
              const __half* __restrict__ H,  const __half* __restrict__ WV,
              float* __restrict__ out) {
    extern __shared__ __align__(1024) char smem[];
    const uint32_t sb = smem_u32(smem);
    const int tid = threadIdx.x;
    const int lane = tid & 31, warp = tid >> 5;
    const int wm = warp & 3, wn = warp >> 2;
    const int e = blockIdx.z;
    const int bm = blockIdx.y * 128, bn = blockIdx.x * 128;   // N = 1024

    const int lr = tid >> 2, lc = tid & 3;
    const uint32_t swL0 = (uint32_t)(lr * 64 + ((lc ^ ((lr >> 1) & 3)) << 4));
    const uint32_t swL1 = (uint32_t)((lr + 64) * 64 + ((lc ^ (((lr + 64) >> 1) & 3)) << 4));
    const uint32_t cbL = (uint32_t)(lc * 16);

    const int rowA0 = wm * 32 + (lane & 15);
    const uint32_t aOff = (uint32_t)(rowA0 * 64 + (((lane >> 4) ^ ((rowA0 >> 1) & 3)) << 4));
    const int rowB0 = wn * 64 + (lane & 7) + ((lane >> 4) << 3);
    const uint32_t bOff = (uint32_t)(rowB0 * 64 + ((((lane >> 3) & 1) ^ ((rowB0 >> 1) & 3)) << 4));

    float acc[2][8][4];

    // ---- Phase A: dr @ Wr (K = 1024) ----
    {
        #pragma unroll
        for (int i = 0; i < 2; ++i)
            #pragma unroll
            for (int j = 0; j < 8; ++j)
                #pragma unroll
                for (int k = 0; k < 4; ++k) acc[i][j][k] = 0.f;
        const char* A = (const char*)DR + ((size_t)e * 2048 + bm) * 2048;
        const char* B = (const char*)WR + ((size_t)e * 1024 + bn) * 2048;
        gemm_mainloop<32, 2048>(sb, A, B, lr, swL0, swL1, cbL, aOff, bOff, acc);

        // sigmoid -> scratch (fp16, conflict-free pitch)
        #pragma unroll
        for (int mi = 0; mi < 2; ++mi)
            #pragma unroll
            for (int nf = 0; nf < 8; ++nf) {
                const float* c = acc[mi][nf];
                const int lcol = wn * 64 + nf * 8 + (lane & 3) * 2;
                const int lrow0 = wm * 32 + mi * 16 + (lane >> 2);
                #pragma unroll
                for (int hh = 0; hh < 2; ++hh) {
                    const int lrow = lrow0 + hh * 8;
                    float v0 = 1.f / (1.f + __expf(-c[hh * 2 + 0]));
                    float v1 = 1.f / (1.f + __expf(-c[hh * 2 + 1]));
                    uint32_t addr = sb + SCRATCH_OFF + lrow * SCRATCH_PITCH + lcol * 2;
                    __half2 hv = __halves2half2(__float2half(v0), __float2half(v1));
                    asm volatile("st.shared.b32 [%0], %1;" :: "r"(addr),
                                 "r"(*(uint32_t*)&hv) : "memory");
                }
            }
    }
    __syncthreads();   // scratch complete; stage buffers free for phase B

    // ---- Phase B: h @ Wv (K = 2048) ----
    {
        #pragma unroll
        for (int i = 0; i < 2; ++i)
            #pragma unroll
            for (int j = 0; j < 8; ++j)
                #pragma unroll
                for (int k = 0; k < 4; ++k) acc[i][j][k] = 0.f;
        const char* A = (const char*)H  + ((size_t)e * 2048 + bm) * 4096;
        const char* B = (const char*)WV + ((size_t)e * 1024 + bn) * 4096;
        gemm_mainloop<64, 4096>(sb, A, B, lr, swL0, swL1, cbL, aOff, bOff, acc);
    }

    // ---- Epilogue: out[tok] = sigmoid * kv ----
    #pragma unroll
    for (int mi = 0; mi < 2; ++mi)
        #pragma unroll
        for (int nf = 0; nf < 8; ++nf) {
            const float* c = acc[mi][nf];
            const int lcol = wn * 64 + nf * 8 + (lane & 3) * 2;
            const int lrow0 = wm * 32 + mi * 16 + (lane >> 2);
            #pragma unroll
            for (int hh = 0; hh < 2; ++hh) {
                const int lrow = lrow0 + hh * 8;
                const int slot = e * 2048 + bm + lrow;
                const int tokidx = g_slot2tok[slot];
                if (tokidx >= 0) {
                    uint32_t addr = sb + SCRATCH_OFF + lrow * SCRATCH_PITCH + lcol * 2;
                    uint32_t sv;
                    asm volatile("ld.shared.b32 %0, [%1];" : "=r"(sv) : "r"(addr));
                    __half2 sh = *(__half2*)&sv;
                    float v0 = __half2float(__low2half(sh))  * c[hh * 2 + 0];
                    float v1 = __half2float(__high2half(sh)) * c[hh * 2 + 1];
                    *(float2*)&out[(size_t)tokidx * 1024 + bn + lcol] = make_float2(v0, v1);
                }
            }
        }
}

// ---------------------------------------------------------------------------
// Zero-fill for dropped tokens; shift state
// ---------------------------------------------------------------------------
__global__ void zero_dropped_kernel(float* __restrict__ out) {
    const int s = blockIdx.x;
    if (g_tok2slot[s] != DROPPED) return;
    const int j = threadIdx.x * 4;
    *(float4*)&out[(size_t)s * Mm + j] = make_float4(0.f, 0.f, 0.f, 0.f);
}
__global__ void shift_kernel(const float* __restrict__ x, float* __restrict__ out) {
    const int b = blockIdx.x;
    const int j = threadIdx.x * 4;
    *(float4*)&out[(size_t)Ss * Mm + (size_t)b * Mm + j] =
        *(const float4*)&x[((size_t)b * Tt + (Tt - 1)) * Mm + j];
}

// ---------------------------------------------------------------------------
// Host
// ---------------------------------------------------------------------------
extern "C" void kernel_launch(void* const* d_in, const int* in_sizes, int n_in,
                              void* d_out, int out_size) {
    const float* x     = (const float*)d_in[0];
    const int*   tok   = (const int*)  d_in[1];
    const float* shift = (const float*)d_in[2];
    const float* maak  = (const float*)d_in[3];
    const float* maar  = (const float*)d_in[4];
    const float* Wk    = (const float*)d_in[5];
    const float* Wv    = (const float*)d_in[6];
    const float* Wr    = (const float*)d_in[7];
    float* out = (float*)d_out;

    void *dkh, *drh, *hh, *wkh, *wvh, *wrh;
    cudaGetSymbolAddress(&dkh, g_dk_h);
    cudaGetSymbolAddress(&drh, g_dr_h);
    cudaGetSymbolAddress(&hh,  g_h_h);
    cudaGetSymbolAddress(&wkh, g_Wk_h);
    cudaGetSymbolAddress(&wvh, g_Wv_h);
    cudaGetSymbolAddress(&wrh, g_Wr_h);

    cudaFuncSetAttribute((const void*)gemm1_kernel,
                         cudaFuncAttributeMaxDynamicSharedMemorySize, GEMM1_SMEM);
    cudaFuncSetAttribute((const void*)gemm23_kernel,
                         cudaFuncAttributeMaxDynamicSharedMemorySize, GEMM23_SMEM);

    route_kernel<<<1, 256>>>(tok);
    dispatch_kernel<<<ECAP, 256>>>(x, shift, maak, maar);
    wconv_fp16_kernel<<<dim3(64, 16, 8), dim3(32, 8)>>>(Wk, (__half*)wkh, 1024, 2048);
    wconv_fp16_kernel<<<dim3(32, 32, 8), dim3(32, 8)>>>(Wv, (__half*)wvh, 2048, 1024);
    wconv_fp16_kernel<<<dim3(32, 16, 8), dim3(32, 8)>>>(Wr, (__half*)wrh, 1024, 1024);

    // h = relu^2(dk @ Wk): K=1024, N=2048
    gemm1_kernel<<<dim3(16, 16, 8), 256, GEMM1_SMEM>>>(
        (const __half*)dkh, (const __half*)wkh, (__half*)hh);
    // out[tok] = sigmoid(dr @ Wr) * (h @ Wv)   — fused, no kv/r buffers
    gemm23_kernel<<<dim3(8, 16, 8), 256, GEMM23_SMEM>>>(
        (const __half*)drh, (const __half*)wrh,
        (const __half*)hh,  (const __half*)wvh, out);

    zero_dropped_kernel<<<Ss, 256>>>(out);
    if ((size_t)out_size >= (size_t)Ss * Mm + (size_t)Bb * Mm)
        shift_kernel<<<Bb, 256>>>(x, out);
}

// round 14
// speedup vs baseline: 1.2239x; 1.0525x over previous
#include <cuda_runtime.h>
#include <cuda_fp16.h>
#include <stdint.h>

// ---------------------------------------------------------------------------
// Problem constants
// ---------------------------------------------------------------------------
#define Bb 8
#define Tt 2048
#define Mm 1024
#define Ff 2048
#define Ee 8
#define Ss 16384
#define CAP 2048
#define ECAP 16384
#define DROPPED 0x7FFFFFFF

// All single-term fp16 storage (hi):
__device__ __align__(128) __half g_dk_h[(size_t)ECAP * 1024];
__device__ __align__(128) __half g_dr_h[(size_t)ECAP * 1024];
__device__ __align__(128) __half g_h_h [(size_t)ECAP * 2048];
__device__ __align__(128) __half g_Wk_h[(size_t)Ee * 2048 * 1024];
__device__ __align__(128) __half g_Wv_h[(size_t)Ee * 1024 * 2048];
__device__ __align__(128) __half g_Wr_h[(size_t)Ee * 1024 * 1024];
__device__ int g_slot2tok[ECAP];
__device__ int g_tok2slot[Ss];

// ---------------------------------------------------------------------------
// PTX helpers
// ---------------------------------------------------------------------------
__device__ __forceinline__ uint32_t smem_u32(const void* p) {
    uint32_t a;
    asm("{ .reg .u64 t; cvta.to.shared.u64 t, %1; cvt.u32.u64 %0, t; }" : "=r"(a) : "l"(p));
    return a;
}
__device__ __forceinline__ void cp16(uint32_t s, const void* g) {
    asm volatile("cp.async.cg.shared.global [%0], [%1], 16;" :: "r"(s), "l"(g) : "memory");
}
#define CP_COMMIT() asm volatile("cp.async.commit_group;" ::: "memory")
#define CP_WAIT1()  asm volatile("cp.async.wait_group 1;" ::: "memory")
#define CP_WAIT0()  asm volatile("cp.async.wait_group 0;" ::: "memory")

#define LDSM_X4(r, a) \
    asm volatile("ldmatrix.sync.aligned.m8n8.x4.shared.b16 {%0,%1,%2,%3}, [%4];" \
        : "=r"((r)[0]), "=r"((r)[1]), "=r"((r)[2]), "=r"((r)[3]) : "r"(a))

__device__ __forceinline__ void mma_fp16(float* c, const uint32_t* a,
                                         uint32_t b0, uint32_t b1) {
    asm volatile(
        "mma.sync.aligned.m16n8k16.row.col.f32.f16.f16.f32 "
        "{%0,%1,%2,%3}, {%4,%5,%6,%7}, {%8,%9}, {%0,%1,%2,%3};"
        : "+f"(c[0]), "+f"(c[1]), "+f"(c[2]), "+f"(c[3])
        : "r"(a[0]), "r"(a[1]), "r"(a[2]), "r"(a[3]), "r"(b0), "r"(b1));
}

// ---------------------------------------------------------------------------
// Routing
// ---------------------------------------------------------------------------
__global__ void route_kernel(const int* __restrict__ tok) {
    __shared__ int cnt[256][8];
    const int t = threadIdx.x;
    for (int i = t; i < ECAP; i += 256) g_slot2tok[i] = -1;
    const int base = t * 64;
    int c[8] = {0,0,0,0,0,0,0,0};
    for (int i = 0; i < 64; ++i) { int e = (tok[base + i] * 5099) & 7; c[e]++; }
    #pragma unroll
    for (int e = 0; e < 8; ++e) cnt[t][e] = c[e];
    __syncthreads();
    if (t < 8) {
        int run = 0;
        for (int j = 0; j < 256; ++j) { int v = cnt[j][t]; cnt[j][t] = run; run += v; }
    }
    __syncthreads();
    int run[8];
    #pragma unroll
    for (int e = 0; e < 8; ++e) run[e] = cnt[t][e];
    for (int i = 0; i < 64; ++i) {
        int s = base + i;
        int e = (tok[s] * 5099) & 7;
        int pos = run[e]++;
        if (pos < CAP) { int slot = e * CAP + pos; g_tok2slot[s] = slot; g_slot2tok[slot] = s; }
        else g_tok2slot[s] = DROPPED;
    }
}

// ---------------------------------------------------------------------------
// Dispatch: token-shift mix; dk & dr fp16 hi only
// ---------------------------------------------------------------------------
__global__ void dispatch_kernel(const float* __restrict__ x,
                                const float* __restrict__ shift,
                                const float* __restrict__ maak,
                                const float* __restrict__ maar) {
    const int slot = blockIdx.x;
    const int j = threadIdx.x * 4;
    __half* rk = g_dk_h + (size_t)slot * 1024;
    __half* rr = g_dr_h + (size_t)slot * 1024;
    const int tokidx = g_slot2tok[slot];
    float4 dk, dr;
    if (tokidx < 0) {
        dk = dr = make_float4(0.f, 0.f, 0.f, 0.f);
    } else {
        const int b = tokidx / Tt;
        const int t = tokidx % Tt;
        float4 xv = *(const float4*)&x[(size_t)tokidx * Mm + j];
        float4 xp;
        if (t == 0) xp = *(const float4*)&shift[(size_t)b * Mm + j];
        else        xp = *(const float4*)&x[(size_t)(tokidx - 1) * Mm + j];
        float4 mk = *(const float4*)&maak[j];
        float4 mr = *(const float4*)&maar[j];
        float4 dx = make_float4(xp.x - xv.x, xp.y - xv.y, xp.z - xv.z, xp.w - xv.w);
        dk = make_float4(fmaf(dx.x, mk.x, xv.x), fmaf(dx.y, mk.y, xv.y),
                         fmaf(dx.z, mk.z, xv.z), fmaf(dx.w, mk.w, xv.w));
        dr = make_float4(fmaf(dx.x, mr.x, xv.x), fmaf(dx.y, mr.y, xv.y),
                         fmaf(dx.z, mr.z, xv.z), fmaf(dx.w, mr.w, xv.w));
    }
    *(__half2*)(rk + j)     = __halves2half2(__float2half(dk.x), __float2half(dk.y));
    *(__half2*)(rk + j + 2) = __halves2half2(__float2half(dk.z), __float2half(dk.w));
    *(__half2*)(rr + j)     = __halves2half2(__float2half(dr.x), __float2half(dr.y));
    *(__half2*)(rr + j + 2) = __halves2half2(__float2half(dr.z), __float2half(dr.w));
}

// ---------------------------------------------------------------------------
// Weight transpose: W [E][K][N] fp32 -> W' [E][N][K] fp16 (hi only)
// ---------------------------------------------------------------------------
__global__ void wconv_fp16_kernel(const float* __restrict__ W,
                                  __half* __restrict__ out, int K, int N) {
    __shared__ __half tile[64][33];
    const int e = blockIdx.z;
    const float* Wp = W + (size_t)e * K * N;
    __half* op = out + (size_t)e * N * K;
    const int k0 = blockIdx.y * 64, n0 = blockIdx.x * 32;
    const int tx = threadIdx.x, ty = threadIdx.y;   // (32, 8)
    #pragma unroll
    for (int i = 0; i < 8; ++i)
        tile[ty + i * 8][tx] = __float2half(Wp[(size_t)(k0 + ty + i * 8) * N + n0 + tx]);
    __syncthreads();
    #pragma unroll
    for (int j = 0; j < 4; ++j) {
        const int n = ty + j * 8;
        __half2 v = __halves2half2(tile[tx * 2][n], tile[tx * 2 + 1][n]);
        *(__half2*)&op[(size_t)(n0 + n) * K + k0 + tx * 2] = v;
    }
}

// ---------------------------------------------------------------------------
// GEMM mainloop, k=64-deep stages: 128x128 tile, 256 thr, 8 warps (4M x 2N),
// warp 32x64. Stage = A 16KB + B 16KB = 32KB (128B rows, SW128 swizzle),
// 3 stages, wait_group 1. Per kt: 4 ks sub-iterations of k=16.
// ---------------------------------------------------------------------------
constexpr int STAGE = 32768;
constexpr int BOFF  = 16384;
constexpr int GEMM_SMEM = 3 * STAGE;   // 98304

template<int KT, int ROW_B>
__device__ __forceinline__ void gemm_mainloop(
    uint32_t sb, const char* A, const char* B, float acc[2][8][4])
{
    const int tid = threadIdx.x;
    const int lane = tid & 31, warp = tid >> 5;
    const int wm = warp & 3, wn = warp >> 2;

    // loader: 256 threads, 8x16B units per 128B row; 4 rows/thread/region
    const int lrow = tid >> 3, lunit = tid & 7;
    const uint32_t ldst = (uint32_t)(lrow * 128 + ((lunit ^ (lrow & 7)) << 4));
    const uint32_t lsrc = (uint32_t)(lunit * 16);

    auto load_stage = [&](int st, int kt) {
        const int colB = kt * 128;
        const uint32_t b = sb + st * STAGE;
        #pragma unroll
        for (int i = 0; i < 4; ++i)   // +32 rows: (row&7) invariant
            cp16(b + ldst + i * 4096,
                 A + (size_t)(lrow + i * 32) * ROW_B + colB + lsrc);
        #pragma unroll
        for (int i = 0; i < 4; ++i)
            cp16(b + BOFF + ldst + i * 4096,
                 B + (size_t)(lrow + i * 32) * ROW_B + colB + lsrc);
    };

    // ldsm addressing (128B rows)
    const int aRow = wm * 32 + (lane & 15);
    const int aX = aRow & 7, aH = lane >> 4;
    const int bRow = wn * 64 + (lane & 7) + ((lane >> 4) << 3);
    const int bX = bRow & 7, bH = (lane >> 3) & 1;

    load_stage(0, 0); CP_COMMIT();
    load_stage(1, 1); CP_COMMIT();

    for (int kt = 0; kt < KT; ++kt) {
        CP_WAIT1();
        __syncthreads();
        if (kt + 2 < KT) load_stage((kt + 2) % 3, kt + 2);
        CP_COMMIT();

        const uint32_t stb = sb + (kt % 3) * STAGE;
        #pragma unroll
        for (int ks = 0; ks < 4; ++ks) {
            uint32_t a[2][4];
            #pragma unroll
            for (int mi = 0; mi < 2; ++mi)
                LDSM_X4(a[mi], stb + (uint32_t)((aRow + mi * 16) * 128 +
                                                (((ks * 2 + aH) ^ aX) << 4)));
            uint32_t b[4][4];
            #pragma unroll
            for (int nf2 = 0; nf2 < 4; ++nf2)
                LDSM_X4(b[nf2], stb + BOFF + (uint32_t)((bRow + nf2 * 16) * 128 +
                                                        (((ks * 2 + bH) ^ bX) << 4)));
            #pragma unroll
            for (int mi = 0; mi < 2; ++mi)
                #pragma unroll
                for (int nf2 = 0; nf2 < 4; ++nf2) {
                    mma_fp16(acc[mi][nf2 * 2 + 0], a[mi], b[nf2][0], b[nf2][1]);
                    mma_fp16(acc[mi][nf2 * 2 + 1], a[mi], b[nf2][2], b[nf2][3]);
                }
        }
    }
    CP_WAIT0();
}

// ---------------------------------------------------------------------------
// GEMM1: h = relu^2(dk @ Wk), fp16 out.  K=1024 (KT=8... K/64=16), N=2048.
// ---------------------------------------------------------------------------
__global__ void __launch_bounds__(256, 2)
gemm1_kernel(const __half* __restrict__ Ag, const __half* __restrict__ Bg,
             __half* __restrict__ Cb) {
    constexpr int N = 2048, ROW_B = 2048, KT = 16;   // K=1024: 16 x 64
    extern __shared__ __align__(1024) char smem[];
    const uint32_t sb = smem_u32(smem);
    const int tid = threadIdx.x;
    const int lane = tid & 31, warp = tid >> 5;
    const int wm = warp & 3, wn = warp >> 2;
    const int e = blockIdx.z;
    const int bm = blockIdx.y * 128, bn = blockIdx.x * 128;

    const char* A = (const char*)Ag + ((size_t)e * 2048 + bm) * ROW_B;
    const char* B = (const char*)Bg + ((size_t)e * N + bn) * ROW_B;

    float acc[2][8][4];
    #pragma unroll
    for (int i = 0; i < 2; ++i)
        #pragma unroll
        for (int j = 0; j < 8; ++j)
            #pragma unroll
            for (int k = 0; k < 4; ++k) acc[i][j][k] = 0.f;

    gemm_mainloop<KT, ROW_B>(sb, A, B, acc);

    #pragma unroll
    for (int mi = 0; mi < 2; ++mi)
        #pragma unroll
        for (int nf = 0; nf < 8; ++nf) {
            const float* c = acc[mi][nf];
            const int col = bn + wn * 64 + nf * 8 + (lane & 3) * 2;
            const int row0 = bm + wm * 32 + mi * 16 + (lane >> 2);
            #pragma unroll
            for (int hh = 0; hh < 2; ++hh) {
                const int row = row0 + hh * 8;
                float v0 = c[hh * 2 + 0], v1 = c[hh * 2 + 1];
                v0 = v0 > 0.f ? v0 * v0 : 0.f;
                v1 = v1 > 0.f ? v1 * v1 : 0.f;
                __half* p = Cb + ((size_t)e * 2048 + row) * (size_t)N + col;
                *(__half2*)p = __halves2half2(__float2half(v0), __float2half(v1));
            }
        }
}

// ---------------------------------------------------------------------------
// GEMM23 fused: Phase A sigmoid(dr @ Wr) -> REGISTERS (fp16x2),
// Phase B h @ Wv, epilogue out[tok] = sig * acc. No smem scratch.
// ---------------------------------------------------------------------------
__global__ void __launch_bounds__(256, 2)
gemm23_kernel(const __half* __restrict__ DR, const __half* __restrict__ WR,
              const __half* __restrict__ H,  const __half* __restrict__ WV,
              float* __restrict__ out) {
    extern __shared__ __align__(1024) char smem[];
    const uint32_t sb = smem_u32(smem);
    const int tid = threadIdx.x;
    const int lane = tid & 31, warp = tid >> 5;
    const int wm = warp & 3, wn = warp >> 2;
    const int e = blockIdx.z;
    const int bm = blockIdx.y * 128, bn = blockIdx.x * 128;   // N = 1024

    float acc[2][8][4];
    uint32_t sig[2][8][2];   // fp16x2-packed sigmoid values

    // ---- Phase A: dr @ Wr (K = 1024, KT = 16) ----
    {
        #pragma unroll
        for (int i = 0; i < 2; ++i)
            #pragma unroll
            for (int j = 0; j < 8; ++j)
                #pragma unroll
                for (int k = 0; k < 4; ++k) acc[i][j][k] = 0.f;
        const char* A = (const char*)DR + ((size_t)e * 2048 + bm) * 2048;
        const char* B = (const char*)WR + ((size_t)e * 1024 + bn) * 2048;
        gemm_mainloop<16, 2048>(sb, A, B, acc);

        #pragma unroll
        for (int mi = 0; mi < 2; ++mi)
            #pragma unroll
            for (int nf = 0; nf < 8; ++nf)
                #pragma unroll
                for (int hh = 0; hh < 2; ++hh) {
                    float v0 = 1.f / (1.f + __expf(-acc[mi][nf][hh * 2 + 0]));
                    float v1 = 1.f / (1.f + __expf(-acc[mi][nf][hh * 2 + 1]));
                    __half2 hv = __halves2half2(__float2half(v0), __float2half(v1));
                    sig[mi][nf][hh] = *(uint32_t*)&hv;
                }
    }
    __syncthreads();   // all warps done with phase-A stages before reuse

    // ---- Phase B: h @ Wv (K = 2048, KT = 32) ----
    {
        #pragma unroll
        for (int i = 0; i < 2; ++i)
            #pragma unroll
            for (int j = 0; j < 8; ++j)
                #pragma unroll
                for (int k = 0; k < 4; ++k) acc[i][j][k] = 0.f;
        const char* A = (const char*)H  + ((size_t)e * 2048 + bm) * 4096;
        const char* B = (const char*)WV + ((size_t)e * 1024 + bn) * 4096;
        gemm_mainloop<32, 4096>(sb, A, B, acc);
    }

    // ---- Epilogue: out[tok] = sigmoid * kv ----
    #pragma unroll
    for (int mi = 0; mi < 2; ++mi)
        #pragma unroll
        for (int nf = 0; nf < 8; ++nf) {
            const int lcol = wn * 64 + nf * 8 + (lane & 3) * 2;
            const int lrow0 = wm * 32 + mi * 16 + (lane >> 2);
            #pragma unroll
            for (int hh = 0; hh < 2; ++hh) {
                const int lrow = lrow0 + hh * 8;
                const int slot = e * 2048 + bm + lrow;
                const int tokidx = g_slot2tok[slot];
                if (tokidx >= 0) {
                    __half2 sh = *(__half2*)&sig[mi][nf][hh];
                    float v0 = __half2float(__low2half(sh))  * acc[mi][nf][hh * 2 + 0];
                    float v1 = __half2float(__high2half(sh)) * acc[mi][nf][hh * 2 + 1];
                    *(float2*)&out[(size_t)tokidx * 1024 + bn + lcol] = make_float2(v0, v1);
                }
            }
        }
}

// ---------------------------------------------------------------------------
// Zero-fill for dropped tokens; shift state
// ---------------------------------------------------------------------------
__global__ void zero_dropped_kernel(float* __restrict__ out) {
    const int s = blockIdx.x;
    if (g_tok2slot[s] != DROPPED) return;
    const int j = threadIdx.x * 4;
    *(float4*)&out[(size_t)s * Mm + j] = make_float4(0.f, 0.f, 0.f, 0.f);
}
__global__ void shift_kernel(const float* __restrict__ x, float* __restrict__ out) {
    const int b = blockIdx.x;
    const int j = threadIdx.x * 4;
    *(float4*)&out[(size_t)Ss * Mm + (size_t)b * Mm + j] =
        *(const float4*)&x[((size_t)b * Tt + (Tt - 1)) * Mm + j];
}

// ---------------------------------------------------------------------------
// Host
// ---------------------------------------------------------------------------
extern "C" void kernel_launch(void* const* d_in, const int* in_sizes, int n_in,
                              void* d_out, int out_size) {
    const float* x     = (const float*)d_in[0];
    const int*   tok   = (const int*)  d_in[1];
    const float* shift = (const float*)d_in[2];
    const float* maak  = (const float*)d_in[3];
    const float* maar  = (const float*)d_in[4];
    const float* Wk    = (const float*)d_in[5];
    const float* Wv    = (const float*)d_in[6];
    const float* Wr    = (const float*)d_in[7];
    float* out = (float*)d_out;

    void *dkh, *drh, *hh, *wkh, *wvh, *wrh;
    cudaGetSymbolAddress(&dkh, g_dk_h);
    cudaGetSymbolAddress(&drh, g_dr_h);
    cudaGetSymbolAddress(&hh,  g_h_h);
    cudaGetSymbolAddress(&wkh, g_Wk_h);
    cudaGetSymbolAddress(&wvh, g_Wv_h);
    cudaGetSymbolAddress(&wrh, g_Wr_h);

    cudaFuncSetAttribute((const void*)gemm1_kernel,
                         cudaFuncAttributeMaxDynamicSharedMemorySize, GEMM_SMEM);
    cudaFuncSetAttribute((const void*)gemm23_kernel,
                         cudaFuncAttributeMaxDynamicSharedMemorySize, GEMM_SMEM);

    route_kernel<<<1, 256>>>(tok);
    dispatch_kernel<<<ECAP, 256>>>(x, shift, maak, maar);
    wconv_fp16_kernel<<<dim3(64, 16, 8), dim3(32, 8)>>>(Wk, (__half*)wkh, 1024, 2048);
    wconv_fp16_kernel<<<dim3(32, 32, 8), dim3(32, 8)>>>(Wv, (__half*)wvh, 2048, 1024);
    wconv_fp16_kernel<<<dim3(32, 16, 8), dim3(32, 8)>>>(Wr, (__half*)wrh, 1024, 1024);

    // h = relu^2(dk @ Wk): K=1024, N=2048
    gemm1_kernel<<<dim3(16, 16, 8), 256, GEMM_SMEM>>>(
        (const __half*)dkh, (const __half*)wkh, (__half*)hh);
    // out[tok] = sigmoid(dr @ Wr) * (h @ Wv)  — fused
    gemm23_kernel<<<dim3(8, 16, 8), 256, GEMM_SMEM>>>(
        (const __half*)drh, (const __half*)wrh,
        (const __half*)hh,  (const __half*)wvh, out);

    zero_dropped_kernel<<<Ss, 256>>>(out);
    if ((size_t)out_size >= (size_t)Ss * Mm + (size_t)Bb * Mm)
        shift_kernel<<<Bb, 256>>>(x, out);
}

// round 15
// speedup vs baseline: 1.2313x; 1.0060x over previous
#include <cuda_runtime.h>
#include <cuda_fp16.h>
#include <stdint.h>

// ---------------------------------------------------------------------------
// Problem constants
// ---------------------------------------------------------------------------
#define Bb 8
#define Tt 2048
#define Mm 1024
#define Ff 2048
#define Ee 8
#define Ss 16384
#define CAP 2048
#define ECAP 16384
#define DROPPED 0x7FFFFFFF

// All single-term fp16 storage (hi):
__device__ __align__(128) __half g_dk_h[(size_t)ECAP * 1024];
__device__ __align__(128) __half g_dr_h[(size_t)ECAP * 1024];
__device__ __align__(128) __half g_h_h [(size_t)ECAP * 2048];
__device__ __align__(128) __half g_Wk_h[(size_t)Ee * 2048 * 1024];
__device__ __align__(128) __half g_Wv_h[(size_t)Ee * 1024 * 2048];
__device__ __align__(128) __half g_Wr_h[(size_t)Ee * 1024 * 1024];
__device__ int g_slot2tok[ECAP];
__device__ int g_tok2slot[Ss];

// ---------------------------------------------------------------------------
// PTX helpers
// ---------------------------------------------------------------------------
__device__ __forceinline__ uint32_t smem_u32(const void* p) {
    uint32_t a;
    asm("{ .reg .u64 t; cvta.to.shared.u64 t, %1; cvt.u32.u64 %0, t; }" : "=r"(a) : "l"(p));
    return a;
}
__device__ __forceinline__ void cp16(uint32_t s, const void* g) {
    asm volatile("cp.async.cg.shared.global [%0], [%1], 16;" :: "r"(s), "l"(g) : "memory");
}
#define CP_COMMIT() asm volatile("cp.async.commit_group;" ::: "memory")
#define CP_WAIT1()  asm volatile("cp.async.wait_group 1;" ::: "memory")
#define CP_WAIT0()  asm volatile("cp.async.wait_group 0;" ::: "memory")

#define LDSM_X4(r, a) \
    asm volatile("ldmatrix.sync.aligned.m8n8.x4.shared.b16 {%0,%1,%2,%3}, [%4];" \
        : "=r"((r)[0]), "=r"((r)[1]), "=r"((r)[2]), "=r"((r)[3]) : "r"(a))

__device__ __forceinline__ void mma_fp16(float* c, const uint32_t* a,
                                         uint32_t b0, uint32_t b1) {
    asm volatile(
        "mma.sync.aligned.m16n8k16.row.col.f32.f16.f16.f32 "
        "{%0,%1,%2,%3}, {%4,%5,%6,%7}, {%8,%9}, {%0,%1,%2,%3};"
        : "+f"(c[0]), "+f"(c[1]), "+f"(c[2]), "+f"(c[3])
        : "r"(a[0]), "r"(a[1]), "r"(a[2]), "r"(a[3]), "r"(b0), "r"(b1));
}

// ---------------------------------------------------------------------------
// Routing
// ---------------------------------------------------------------------------
__global__ void route_kernel(const int* __restrict__ tok) {
    __shared__ int cnt[256][8];
    const int t = threadIdx.x;
    for (int i = t; i < ECAP; i += 256) g_slot2tok[i] = -1;
    const int base = t * 64;
    int c[8] = {0,0,0,0,0,0,0,0};
    for (int i = 0; i < 64; ++i) { int e = (tok[base + i] * 5099) & 7; c[e]++; }
    #pragma unroll
    for (int e = 0; e < 8; ++e) cnt[t][e] = c[e];
    __syncthreads();
    if (t < 8) {
        int run = 0;
        for (int j = 0; j < 256; ++j) { int v = cnt[j][t]; cnt[j][t] = run; run += v; }
    }
    __syncthreads();
    int run[8];
    #pragma unroll
    for (int e = 0; e < 8; ++e) run[e] = cnt[t][e];
    for (int i = 0; i < 64; ++i) {
        int s = base + i;
        int e = (tok[s] * 5099) & 7;
        int pos = run[e]++;
        if (pos < CAP) { int slot = e * CAP + pos; g_tok2slot[s] = slot; g_slot2tok[slot] = s; }
        else g_tok2slot[s] = DROPPED;
    }
}

// ---------------------------------------------------------------------------
// Dispatch: token-shift mix; dk & dr fp16 hi only
// ---------------------------------------------------------------------------
__global__ void dispatch_kernel(const float* __restrict__ x,
                                const float* __restrict__ shift,
                                const float* __restrict__ maak,
                                const float* __restrict__ maar) {
    const int slot = blockIdx.x;
    const int j = threadIdx.x * 4;
    __half* rk = g_dk_h + (size_t)slot * 1024;
    __half* rr = g_dr_h + (size_t)slot * 1024;
    const int tokidx = g_slot2tok[slot];
    float4 dk, dr;
    if (tokidx < 0) {
        dk = dr = make_float4(0.f, 0.f, 0.f, 0.f);
    } else {
        const int b = tokidx / Tt;
        const int t = tokidx % Tt;
        float4 xv = *(const float4*)&x[(size_t)tokidx * Mm + j];
        float4 xp;
        if (t == 0) xp = *(const float4*)&shift[(size_t)b * Mm + j];
        else        xp = *(const float4*)&x[(size_t)(tokidx - 1) * Mm + j];
        float4 mk = *(const float4*)&maak[j];
        float4 mr = *(const float4*)&maar[j];
        float4 dx = make_float4(xp.x - xv.x, xp.y - xv.y, xp.z - xv.z, xp.w - xv.w);
        dk = make_float4(fmaf(dx.x, mk.x, xv.x), fmaf(dx.y, mk.y, xv.y),
                         fmaf(dx.z, mk.z, xv.z), fmaf(dx.w, mk.w, xv.w));
        dr = make_float4(fmaf(dx.x, mr.x, xv.x), fmaf(dx.y, mr.y, xv.y),
                         fmaf(dx.z, mr.z, xv.z), fmaf(dx.w, mr.w, xv.w));
    }
    *(__half2*)(rk + j)     = __halves2half2(__float2half(dk.x), __float2half(dk.y));
    *(__half2*)(rk + j + 2) = __halves2half2(__float2half(dk.z), __float2half(dk.w));
    *(__half2*)(rr + j)     = __halves2half2(__float2half(dr.x), __float2half(dr.y));
    *(__half2*)(rr + j + 2) = __halves2half2(__float2half(dr.z), __float2half(dr.w));
}

// ---------------------------------------------------------------------------
// Weight transpose v2: W [E][K][N] fp32 -> W' [E][N][K] fp16 (hi only)
// 64k x 64n tile per block (16KB staged), 256 thr (32,8).
// smem row stride 65 halves (odd) -> conflict-free on both phases.
// ---------------------------------------------------------------------------
__global__ void wconv_fp16_kernel(const float* __restrict__ W,
                                  __half* __restrict__ out, int K, int N) {
    __shared__ __half tile[64][65];
    const int e = blockIdx.z;
    const float* Wp = W + (size_t)e * K * N;
    __half* op = out + (size_t)e * N * K;
    const int k0 = blockIdx.y * 64, n0 = blockIdx.x * 64;
    const int tx = threadIdx.x, ty = threadIdx.y;   // (32, 8)

    // read: rows = k (coalesced across n), two 32-col groups
    #pragma unroll
    for (int i = 0; i < 8; ++i) {
        const int k = ty + i * 8;
        const float* src = &Wp[(size_t)(k0 + k) * N + n0 + tx];
        tile[k][tx]      = __float2half(src[0]);
        tile[k][tx + 32] = __float2half(src[32]);
    }
    __syncthreads();

    // write: rows = n (coalesced across k via half2)
    #pragma unroll
    for (int j = 0; j < 8; ++j) {
        const int n = ty + j * 8;
        __half2 v = __halves2half2(tile[tx * 2][n], tile[tx * 2 + 1][n]);
        *(__half2*)&op[(size_t)(n0 + n) * K + k0 + tx * 2] = v;
    }
}

// ---------------------------------------------------------------------------
// GEMM mainloop, k=64-deep stages: 128x128 tile, 256 thr, 8 warps (4M x 2N),
// warp 32x64. Stage = A 16KB + B 16KB = 32KB (128B rows, SW128 swizzle),
// 3 stages, wait_group 1. Per kt: 4 ks sub-iterations of k=16.
// ---------------------------------------------------------------------------
constexpr int STAGE = 32768;
constexpr int BOFF  = 16384;
constexpr int GEMM_SMEM = 3 * STAGE;   // 98304

template<int KT, int ROW_B>
__device__ __forceinline__ void gemm_mainloop(
    uint32_t sb, const char* A, const char* B, float acc[2][8][4])
{
    const int tid = threadIdx.x;
    const int lane = tid & 31, warp = tid >> 5;
    const int wm = warp & 3, wn = warp >> 2;

    const int lrow = tid >> 3, lunit = tid & 7;
    const uint32_t ldst = (uint32_t)(lrow * 128 + ((lunit ^ (lrow & 7)) << 4));
    const uint32_t lsrc = (uint32_t)(lunit * 16);

    auto load_stage = [&](int st, int kt) {
        const int colB = kt * 128;
        const uint32_t b = sb + st * STAGE;
        #pragma unroll
        for (int i = 0; i < 4; ++i)
            cp16(b + ldst + i * 4096,
                 A + (size_t)(lrow + i * 32) * ROW_B + colB + lsrc);
        #pragma unroll
        for (int i = 0; i < 4; ++i)
            cp16(b + BOFF + ldst + i * 4096,
                 B + (size_t)(lrow + i * 32) * ROW_B + colB + lsrc);
    };

    const int aRow = wm * 32 + (lane & 15);
    const int aX = aRow & 7, aH = lane >> 4;
    const int bRow = wn * 64 + (lane & 7) + ((lane >> 4) << 3);
    const int bX = bRow & 7, bH = (lane >> 3) & 1;

    load_stage(0, 0); CP_COMMIT();
    load_stage(1, 1); CP_COMMIT();

    for (int kt = 0; kt < KT; ++kt) {
        CP_WAIT1();
        __syncthreads();
        if (kt + 2 < KT) load_stage((kt + 2) % 3, kt + 2);
        CP_COMMIT();

        const uint32_t stb = sb + (kt % 3) * STAGE;
        #pragma unroll
        for (int ks = 0; ks < 4; ++ks) {
            uint32_t a[2][4];
            #pragma unroll
            for (int mi = 0; mi < 2; ++mi)
                LDSM_X4(a[mi], stb + (uint32_t)((aRow + mi * 16) * 128 +
                                                (((ks * 2 + aH) ^ aX) << 4)));
            uint32_t b[4][4];
            #pragma unroll
            for (int nf2 = 0; nf2 < 4; ++nf2)
                LDSM_X4(b[nf2], stb + BOFF + (uint32_t)((bRow + nf2 * 16) * 128 +
                                                        (((ks * 2 + bH) ^ bX) << 4)));
            #pragma unroll
            for (int mi = 0; mi < 2; ++mi)
                #pragma unroll
                for (int nf2 = 0; nf2 < 4; ++nf2) {
                    mma_fp16(acc[mi][nf2 * 2 + 0], a[mi], b[nf2][0], b[nf2][1]);
                    mma_fp16(acc[mi][nf2 * 2 + 1], a[mi], b[nf2][2], b[nf2][3]);
                }
        }
    }
    CP_WAIT0();
}

// ---------------------------------------------------------------------------
// GEMM1: h = relu^2(dk @ Wk), fp16 out. K=1024 (KT=16), N=2048.
// ---------------------------------------------------------------------------
__global__ void __launch_bounds__(256, 2)
gemm1_kernel(const __half* __restrict__ Ag, const __half* __restrict__ Bg,
             __half* __restrict__ Cb) {
    constexpr int N = 2048, ROW_B = 2048, KT = 16;
    extern __shared__ __align__(1024) char smem[];
    const uint32_t sb = smem_u32(smem);
    const int tid = threadIdx.x;
    const int lane = tid & 31, warp = tid >> 5;
    const int wm = warp & 3, wn = warp >> 2;
    const int e = blockIdx.z;
    const int bm = blockIdx.y * 128, bn = blockIdx.x * 128;

    const char* A = (const char*)Ag + ((size_t)e * 2048 + bm) * ROW_B;
    const char* B = (const char*)Bg + ((size_t)e * N + bn) * ROW_B;

    float acc[2][8][4];
    #pragma unroll
    for (int i = 0; i < 2; ++i)
        #pragma unroll
        for (int j = 0; j < 8; ++j)
            #pragma unroll
            for (int k = 0; k < 4; ++k) acc[i][j][k] = 0.f;

    gemm_mainloop<KT, ROW_B>(sb, A, B, acc);

    #pragma unroll
    for (int mi = 0; mi < 2; ++mi)
        #pragma unroll
        for (int nf = 0; nf < 8; ++nf) {
            const float* c = acc[mi][nf];
            const int col = bn + wn * 64 + nf * 8 + (lane & 3) * 2;
            const int row0 = bm + wm * 32 + mi * 16 + (lane >> 2);
            #pragma unroll
            for (int hh = 0; hh < 2; ++hh) {
                const int row = row0 + hh * 8;
                float v0 = c[hh * 2 + 0], v1 = c[hh * 2 + 1];
                v0 = v0 > 0.f ? v0 * v0 : 0.f;
                v1 = v1 > 0.f ? v1 * v1 : 0.f;
                __half* p = Cb + ((size_t)e * 2048 + row) * (size_t)N + col;
                *(__half2*)p = __halves2half2(__float2half(v0), __float2half(v1));
            }
        }
}

// ---------------------------------------------------------------------------
// GEMM23 fused: Phase A sigmoid(dr @ Wr) -> registers (fp16x2),
// Phase B h @ Wv, epilogue out[tok] = sig * acc.
// ---------------------------------------------------------------------------
__global__ void __launch_bounds__(256, 2)
gemm23_kernel(const __half* __restrict__ DR, const __half* __restrict__ WR,
              const __half* __restrict__ H,  const __half* __restrict__ WV,
              float* __restrict__ out) {
    extern __shared__ __align__(1024) char smem[];
    const uint32_t sb = smem_u32(smem);
    const int tid = threadIdx.x;
    const int lane = tid & 31, warp = tid >> 5;
    const int wm = warp & 3, wn = warp >> 2;
    const int e = blockIdx.z;
    const int bm = blockIdx.y * 128, bn = blockIdx.x * 128;   // N = 1024

    float acc[2][8][4];
    uint32_t sig[2][8][2];

    // ---- Phase A: dr @ Wr (K = 1024, KT = 16) ----
    {
        #pragma unroll
        for (int i = 0; i < 2; ++i)
            #pragma unroll
            for (int j = 0; j < 8; ++j)
                #pragma unroll
                for (int k = 0; k < 4; ++k) acc[i][j][k] = 0.f;
        const char* A = (const char*)DR + ((size_t)e * 2048 + bm) * 2048;
        const char* B = (const char*)WR + ((size_t)e * 1024 + bn) * 2048;
        gemm_mainloop<16, 2048>(sb, A, B, acc);

        #pragma unroll
        for (int mi = 0; mi < 2; ++mi)
            #pragma unroll
            for (int nf = 0; nf < 8; ++nf)
                #pragma unroll
                for (int hh = 0; hh < 2; ++hh) {
                    float v0 = 1.f / (1.f + __expf(-acc[mi][nf][hh * 2 + 0]));
                    float v1 = 1.f / (1.f + __expf(-acc[mi][nf][hh * 2 + 1]));
                    __half2 hv = __halves2half2(__float2half(v0), __float2half(v1));
                    sig[mi][nf][hh] = *(uint32_t*)&hv;
                }
    }
    __syncthreads();

    // ---- Phase B: h @ Wv (K = 2048, KT = 32) ----
    {
        #pragma unroll
        for (int i = 0; i < 2; ++i)
            #pragma unroll
            for (int j = 0; j < 8; ++j)
                #pragma unroll
                for (int k = 0; k < 4; ++k) acc[i][j][k] = 0.f;
        const char* A = (const char*)H  + ((size_t)e * 2048 + bm) * 4096;
        const char* B = (const char*)WV + ((size_t)e * 1024 + bn) * 4096;
        gemm_mainloop<32, 4096>(sb, A, B, acc);
    }

    // ---- Epilogue: out[tok] = sigmoid * kv ----
    #pragma unroll
    for (int mi = 0; mi < 2; ++mi)
        #pragma unroll
        for (int nf = 0; nf < 8; ++nf) {
            const int lcol = wn * 64 + nf * 8 + (lane & 3) * 2;
            const int lrow0 = wm * 32 + mi * 16 + (lane >> 2);
            #pragma unroll
            for (int hh = 0; hh < 2; ++hh) {
                const int lrow = lrow0 + hh * 8;
                const int slot = e * 2048 + bm + lrow;
                const int tokidx = g_slot2tok[slot];
                if (tokidx >= 0) {
                    __half2 sh = *(__half2*)&sig[mi][nf][hh];
                    float v0 = __half2float(__low2half(sh))  * acc[mi][nf][hh * 2 + 0];
                    float v1 = __half2float(__high2half(sh)) * acc[mi][nf][hh * 2 + 1];
                    *(float2*)&out[(size_t)tokidx * 1024 + bn + lcol] = make_float2(v0, v1);
                }
            }
        }
}

// ---------------------------------------------------------------------------
// Cleanup: zero dropped-token rows + shift state, one kernel.
// ---------------------------------------------------------------------------
__global__ void cleanup_kernel(const float* __restrict__ x, float* __restrict__ out,
                               int do_shift) {
    const int s = blockIdx.x;
    const int j = threadIdx.x * 4;
    if (s < Ss) {
        if (g_tok2slot[s] == DROPPED)
            *(float4*)&out[(size_t)s * Mm + j] = make_float4(0.f, 0.f, 0.f, 0.f);
    } else if (do_shift) {
        const int b = s - Ss;
        *(float4*)&out[(size_t)Ss * Mm + (size_t)b * Mm + j] =
            *(const float4*)&x[((size_t)b * Tt + (Tt - 1)) * Mm + j];
    }
}

// ---------------------------------------------------------------------------
// Host
// ---------------------------------------------------------------------------
extern "C" void kernel_launch(void* const* d_in, const int* in_sizes, int n_in,
                              void* d_out, int out_size) {
    const float* x     = (const float*)d_in[0];
    const int*   tok   = (const int*)  d_in[1];
    const float* shift = (const float*)d_in[2];
    const float* maak  = (const float*)d_in[3];
    const float* maar  = (const float*)d_in[4];
    const float* Wk    = (const float*)d_in[5];
    const float* Wv    = (const float*)d_in[6];
    const float* Wr    = (const float*)d_in[7];
    float* out = (float*)d_out;

    void *dkh, *drh, *hh, *wkh, *wvh, *wrh;
    cudaGetSymbolAddress(&dkh, g_dk_h);
    cudaGetSymbolAddress(&drh, g_dr_h);
    cudaGetSymbolAddress(&hh,  g_h_h);
    cudaGetSymbolAddress(&wkh, g_Wk_h);
    cudaGetSymbolAddress(&wvh, g_Wv_h);
    cudaGetSymbolAddress(&wrh, g_Wr_h);

    cudaFuncSetAttribute((const void*)gemm1_kernel,
                         cudaFuncAttributeMaxDynamicSharedMemorySize, GEMM_SMEM);
    cudaFuncSetAttribute((const void*)gemm23_kernel,
                         cudaFuncAttributeMaxDynamicSharedMemorySize, GEMM_SMEM);

    route_kernel<<<1, 256>>>(tok);
    dispatch_kernel<<<ECAP, 256>>>(x, shift, maak, maar);
    // Wk: K=1024, N=2048 -> grid (N/64, K/64, 8)
    wconv_fp16_kernel<<<dim3(32, 16, 8), dim3(32, 8)>>>(Wk, (__half*)wkh, 1024, 2048);
    // Wv: K=2048, N=1024
    wconv_fp16_kernel<<<dim3(16, 32, 8), dim3(32, 8)>>>(Wv, (__half*)wvh, 2048, 1024);
    // Wr: K=1024, N=1024
    wconv_fp16_kernel<<<dim3(16, 16, 8), dim3(32, 8)>>>(Wr, (__half*)wrh, 1024, 1024);

    // h = relu^2(dk @ Wk): K=1024, N=2048
    gemm1_kernel<<<dim3(16, 16, 8), 256, GEMM_SMEM>>>(
        (const __half*)dkh, (const __half*)wkh, (__half*)hh);
    // out[tok] = sigmoid(dr @ Wr) * (h @ Wv)  — fused
    gemm23_kernel<<<dim3(8, 16, 8), 256, GEMM_SMEM>>>(
        (const __half*)drh, (const __half*)wrh,
        (const __half*)hh,  (const __half*)wvh, out);

    const int do_shift = ((size_t)out_size >= (size_t)Ss * Mm + (size_t)Bb * Mm) ? 1 : 0;
    cleanup_kernel<<<Ss + Bb, 256>>>(x, out, do_shift);
}